// round 2
// baseline (speedup 1.0000x reference)
#include <cuda_runtime.h>
#include <cstdint>
#include <cstddef>

// ---------------------------------------------------------------------------
// MinGRU: g = x@Wg.T + bg ; v = x@Wv.T + bv ; d = x@Wd.T + bd
//         x_scan = sigmoid(g)*tanh(v) ; a = 0.001 + 0.998*sigmoid(d)
//         h_t = a_t*h_{t-1} + x_scan_t   (causal scan over S per (b,d))
// B=4, S=4096, D=1024
// ---------------------------------------------------------------------------

#define Bdim 4
#define Sdim 4096
#define Ddim 1024
#define Mdim (Bdim * Sdim)   // 16384

#define NCHUNK 32
#define CHUNK  128           // NCHUNK*CHUNK == Sdim
#define NCH    (Bdim * Ddim) // 4096 channels

// Scratch (allocation-free rule: __device__ globals)
__device__ float g_xs[(size_t)Mdim * Ddim];   // 64 MB
__device__ float g_a [(size_t)Mdim * Ddim];   // 64 MB
__device__ float g_P  [NCHUNK * NCH];
__device__ float g_L  [NCHUNK * NCH];
__device__ float g_cin[NCHUNK * NCH];

// ---------------------------------------------------------------------------
// helpers
// ---------------------------------------------------------------------------
__device__ __forceinline__ uint32_t f2tf(float f) {
    uint32_t r;
    asm("cvt.rna.tf32.f32 %0, %1;" : "=r"(r) : "f"(f));
    return r;
}

__device__ __forceinline__ void mma_tf32(float* c, const uint32_t* a,
                                         uint32_t b0, uint32_t b1) {
    asm volatile(
        "mma.sync.aligned.m16n8k8.row.col.f32.tf32.tf32.f32 "
        "{%0,%1,%2,%3}, {%4,%5,%6,%7}, {%8,%9}, {%0,%1,%2,%3};"
        : "+f"(c[0]), "+f"(c[1]), "+f"(c[2]), "+f"(c[3])
        : "r"(a[0]), "r"(a[1]), "r"(a[2]), "r"(a[3]), "r"(b0), "r"(b1));
}

__device__ __forceinline__ float sigmoidf_(float z) {
    return 1.0f / (1.0f + __expf(-z));
}
__device__ __forceinline__ float tanhf_(float z) {
    // 2*sigmoid(2z)-1 ; saturates correctly for |z| large
    return 2.0f / (1.0f + __expf(-2.0f * z)) - 1.0f;
}

// ---------------------------------------------------------------------------
// Kernel 1: fused triple GEMM (tf32 tensor cores) + activations
//   block tile: BM=128 x BN=64, BK=16 ; 8 warps (4x2), warp tile 32x32
//   3 accumulator sets (g,v,d) share the A (x) tile.
// ---------------------------------------------------------------------------
#define BM 128
#define BN 64
#define BK 16
#define SSTR 20   // smem row stride (floats), conflict-free for frag loads

__global__ __launch_bounds__(256, 1)
void gemm3_act_kernel(const float* __restrict__ x,
                      const float* __restrict__ Wg, const float* __restrict__ bg,
                      const float* __restrict__ Wv, const float* __restrict__ bv,
                      const float* __restrict__ Wd, const float* __restrict__ bd)
{
    __shared__ uint32_t As[BM][SSTR];        // 128x16 (tf32 bits)
    __shared__ uint32_t Bs[3][BN][SSTR];     // 3 x 64x16

    const int m0 = blockIdx.x * BM;   // gridDim.x = 128
    const int n0 = blockIdx.y * BN;   // gridDim.y = 16
    const int tid  = threadIdx.x;
    const int lane = tid & 31;
    const int wid  = tid >> 5;
    const int wm = (wid & 3) * 32;    // warp M origin within block
    const int wn = (wid >> 2) * 32;   // warp N origin within block
    const int grp = lane >> 2;        // groupID  (0..7)
    const int tg  = lane & 3;         // thread in group (0..3)

    const float* Ws[3] = {Wg, Wv, Wd};

    float acc[3][2][4][4];
    #pragma unroll
    for (int w = 0; w < 3; w++)
        #pragma unroll
        for (int mi = 0; mi < 2; mi++)
            #pragma unroll
            for (int ni = 0; ni < 4; ni++)
                #pragma unroll
                for (int r = 0; r < 4; r++) acc[w][mi][ni][r] = 0.0f;

    // per-thread global->reg staging (software pipeline over global latency)
    const int arow = tid >> 2;        // 0..63
    const int akc  = (tid & 3) * 4;   // 0,4,8,12
    float4 pa0, pa1, pb[3];

    auto_dummy: ;
    // load tile at k0 into regs
    #define LOAD_REGS(k0)                                                            \
        do {                                                                         \
            pa0 = *(const float4*)(x + (size_t)(m0 + arow     ) * Ddim + (k0) + akc);\
            pa1 = *(const float4*)(x + (size_t)(m0 + arow + 64) * Ddim + (k0) + akc);\
            _Pragma("unroll")                                                        \
            for (int w = 0; w < 3; w++)                                              \
                pb[w] = *(const float4*)(Ws[w] + (size_t)(n0 + arow) * Ddim + (k0) + akc); \
        } while (0)

    #define STORE_SMEM()                                                             \
        do {                                                                         \
            As[arow     ][akc + 0] = f2tf(pa0.x); As[arow     ][akc + 1] = f2tf(pa0.y); \
            As[arow     ][akc + 2] = f2tf(pa0.z); As[arow     ][akc + 3] = f2tf(pa0.w); \
            As[arow + 64][akc + 0] = f2tf(pa1.x); As[arow + 64][akc + 1] = f2tf(pa1.y); \
            As[arow + 64][akc + 2] = f2tf(pa1.z); As[arow + 64][akc + 3] = f2tf(pa1.w); \
            _Pragma("unroll")                                                        \
            for (int w = 0; w < 3; w++) {                                            \
                Bs[w][arow][akc + 0] = f2tf(pb[w].x);                                \
                Bs[w][arow][akc + 1] = f2tf(pb[w].y);                                \
                Bs[w][arow][akc + 2] = f2tf(pb[w].z);                                \
                Bs[w][arow][akc + 3] = f2tf(pb[w].w);                                \
            }                                                                        \
        } while (0)

    LOAD_REGS(0);
    STORE_SMEM();
    __syncthreads();

    for (int k0 = 0; k0 < Ddim; k0 += BK) {
        const bool has_next = (k0 + BK) < Ddim;
        if (has_next) LOAD_REGS(k0 + BK);

        #pragma unroll
        for (int ks = 0; ks < 2; ks++) {
            const int kb = ks * 8;
            uint32_t afrag[2][4];
            #pragma unroll
            for (int mi = 0; mi < 2; mi++) {
                const int rb = wm + mi * 16;
                afrag[mi][0] = As[rb + grp    ][kb + tg    ];
                afrag[mi][1] = As[rb + grp + 8][kb + tg    ];
                afrag[mi][2] = As[rb + grp    ][kb + tg + 4];
                afrag[mi][3] = As[rb + grp + 8][kb + tg + 4];
            }
            #pragma unroll
            for (int w = 0; w < 3; w++) {
                #pragma unroll
                for (int ni = 0; ni < 4; ni++) {
                    const int nb = wn + ni * 8;
                    const uint32_t b0 = Bs[w][nb + grp][kb + tg    ];
                    const uint32_t b1 = Bs[w][nb + grp][kb + tg + 4];
                    #pragma unroll
                    for (int mi = 0; mi < 2; mi++)
                        mma_tf32(acc[w][mi][ni], afrag[mi], b0, b1);
                }
            }
        }
        __syncthreads();
        if (has_next) {
            STORE_SMEM();
            __syncthreads();
        }
    }

    // epilogue: bias + activations, write x_scan and a
    #pragma unroll
    for (int mi = 0; mi < 2; mi++) {
        const int rbase = m0 + wm + mi * 16 + grp;
        #pragma unroll
        for (int ni = 0; ni < 4; ni++) {
            const int cc = n0 + wn + ni * 8 + tg * 2;
            const float bg0 = bg[cc], bg1 = bg[cc + 1];
            const float bv0 = bv[cc], bv1 = bv[cc + 1];
            const float bd0 = bd[cc], bd1 = bd[cc + 1];
            #pragma unroll
            for (int rr = 0; rr < 2; rr++) {
                const int row = rbase + rr * 8;
                const float gg0 = acc[0][mi][ni][rr * 2 + 0] + bg0;
                const float gg1 = acc[0][mi][ni][rr * 2 + 1] + bg1;
                const float vv0 = acc[1][mi][ni][rr * 2 + 0] + bv0;
                const float vv1 = acc[1][mi][ni][rr * 2 + 1] + bv1;
                const float dd0 = acc[2][mi][ni][rr * 2 + 0] + bd0;
                const float dd1 = acc[2][mi][ni][rr * 2 + 1] + bd1;

                const float xs0 = sigmoidf_(gg0) * tanhf_(vv0);
                const float xs1 = sigmoidf_(gg1) * tanhf_(vv1);
                const float aa0 = 0.001f + 0.998f * sigmoidf_(dd0);
                const float aa1 = 0.001f + 0.998f * sigmoidf_(dd1);

                const size_t off = (size_t)row * Ddim + cc;
                *(float2*)(g_xs + off) = make_float2(xs0, xs1);
                *(float2*)(g_a  + off) = make_float2(aa0, aa1);
            }
        }
    }
}

// ---------------------------------------------------------------------------
// Kernel 2: per-(channel, chunk) reduction: P = prod(a), L = local scan end
//   thread t: chunk = t>>12, ch = t&4095 (b = ch>>10, d = ch&1023)
//   coalesced: consecutive threads = consecutive d
// ---------------------------------------------------------------------------
__global__ void chunk_stats_kernel()
{
    const int t = blockIdx.x * blockDim.x + threadIdx.x;   // 0..131071
    const int ch    = t & (NCH - 1);
    const int chunk = t >> 12;
    const int b = ch >> 10;
    const int d = ch & (Ddim - 1);
    const size_t base = ((size_t)b * Sdim + (size_t)chunk * CHUNK) * Ddim + d;

    float P = 1.0f, L = 0.0f;
    #pragma unroll 8
    for (int i = 0; i < CHUNK; i++) {
        const float a  = g_a [base + (size_t)i * Ddim];
        const float xv = g_xs[base + (size_t)i * Ddim];
        L = fmaf(a, L, xv);
        P *= a;
    }
    g_P[t] = P;   // layout [chunk][ch]
    g_L[t] = L;
}

// ---------------------------------------------------------------------------
// Kernel 3: sequential carry combine over the 32 chunks per channel
// ---------------------------------------------------------------------------
__global__ void carry_kernel()
{
    const int ch = blockIdx.x * blockDim.x + threadIdx.x;  // 0..4095
    float h = 0.0f;
    #pragma unroll
    for (int c = 0; c < NCHUNK; c++) {
        g_cin[c * NCH + ch] = h;                 // carry INTO chunk c
        h = fmaf(g_P[c * NCH + ch], h, g_L[c * NCH + ch]);
    }
}

// ---------------------------------------------------------------------------
// Kernel 4: final scan with carry-in, write output
// ---------------------------------------------------------------------------
__global__ void final_scan_kernel(float* __restrict__ out)
{
    const int t = blockIdx.x * blockDim.x + threadIdx.x;
    const int ch    = t & (NCH - 1);
    const int chunk = t >> 12;
    const int b = ch >> 10;
    const int d = ch & (Ddim - 1);
    const size_t base = ((size_t)b * Sdim + (size_t)chunk * CHUNK) * Ddim + d;

    float h = g_cin[t];
    #pragma unroll 8
    for (int i = 0; i < CHUNK; i++) {
        const size_t off = base + (size_t)i * Ddim;
        const float a  = g_a [off];
        const float xv = g_xs[off];
        h = fmaf(a, h, xv);
        out[off] = h;
    }
}

// ---------------------------------------------------------------------------
extern "C" void kernel_launch(void* const* d_in, const int* in_sizes, int n_in,
                              void* d_out, int out_size)
{
    const float* x  = (const float*)d_in[0];
    const float* Wg = (const float*)d_in[1];
    const float* bg = (const float*)d_in[2];
    const float* Wv = (const float*)d_in[3];
    const float* bv = (const float*)d_in[4];
    const float* Wd = (const float*)d_in[5];
    const float* bd = (const float*)d_in[6];
    float* out = (float*)d_out;

    dim3 g1(Mdim / BM, Ddim / BN);   // 128 x 16
    gemm3_act_kernel<<<g1, 256>>>(x, Wg, bg, Wv, bv, Wd, bd);

    chunk_stats_kernel<<<(NCHUNK * NCH) / 256, 256>>>();   // 512 blocks
    carry_kernel<<<NCH / 256, 256>>>();                    // 16 blocks
    final_scan_kernel<<<(NCHUNK * NCH) / 256, 256>>>(out); // 512 blocks
}

// round 4
// speedup vs baseline: 1.9880x; 1.9880x over previous
#include <cuda_runtime.h>
#include <cuda_fp16.h>
#include <cstdint>
#include <cstddef>

// ===========================================================================
// MinGRU B=4 S=4096 D=1024:
//  g,v,d = x@W{g,v,d}.T + b ; xs = sig(g)*tanh(v); a = 0.001+0.998*sig(d)
//  h_t = a_t h_{t-1} + xs_t  (causal scan over S)
// Round 4: legacy-path fp16 mma.sync (m16n8k16) triple GEMM with 4-stage
// cp.async pipeline (tcgen05 unavailable: harness ptxas targets sm_103
// without the 'a' suffix). Chunked scan unchanged.
// ===========================================================================

#define Bdim 4
#define Sdim 4096
#define Ddim 1024
#define Mdim (Bdim * Sdim)        // 16384

#define NCHUNK 32
#define CHUNK  128
#define NCH    (Bdim * Ddim)      // 4096

// Scratch (__device__ globals; no allocs allowed)
__device__ float  g_xs[(size_t)Mdim * Ddim];        // 64 MB
__device__ float  g_a [(size_t)Mdim * Ddim];        // 64 MB
__device__ __half g_xh[(size_t)Mdim * Ddim];        // 32 MB (fp16 x)
__device__ __half g_wh[(size_t)3 * Ddim * Ddim];    //  6 MB (fp16 Wg,Wv,Wd)
__device__ float  g_P  [NCHUNK * NCH];
__device__ float  g_L  [NCHUNK * NCH];
__device__ float  g_cin[NCHUNK * NCH];

// ---------------------------------------------------------------------------
// helpers
// ---------------------------------------------------------------------------
__device__ __forceinline__ uint32_t smem_u32(const void* p) {
    uint32_t a;
    asm("{ .reg .u64 t; cvta.to.shared.u64 t, %1; cvt.u32.u64 %0, t; }"
        : "=r"(a) : "l"(p));
    return a;
}

__device__ __forceinline__ void cp_async16(uint32_t dst, const void* src) {
    asm volatile("cp.async.cg.shared.global [%0], [%1], 16;"
                 :: "r"(dst), "l"(src) : "memory");
}
#define CP_COMMIT() asm volatile("cp.async.commit_group;" ::: "memory")
#define CP_WAIT2()  asm volatile("cp.async.wait_group 2;"  ::: "memory")

__device__ __forceinline__ void mma_fp16(float* c, const uint32_t* a,
                                         uint32_t b0, uint32_t b1) {
    asm volatile(
        "mma.sync.aligned.m16n8k16.row.col.f32.f16.f16.f32 "
        "{%0,%1,%2,%3}, {%4,%5,%6,%7}, {%8,%9}, {%0,%1,%2,%3};"
        : "+f"(c[0]), "+f"(c[1]), "+f"(c[2]), "+f"(c[3])
        : "r"(a[0]), "r"(a[1]), "r"(a[2]), "r"(a[3]), "r"(b0), "r"(b1));
}

__device__ __forceinline__ float sigmoidf_(float z) { return 1.0f / (1.0f + __expf(-z)); }
__device__ __forceinline__ float tanhf_(float z)    { return 2.0f / (1.0f + __expf(-2.0f * z)) - 1.0f; }

// ---------------------------------------------------------------------------
// Kernel 0: fp32 -> fp16 conversion
// ---------------------------------------------------------------------------
__global__ void f32_to_f16_kernel(const float4* __restrict__ in,
                                  uint2* __restrict__ out, int n4)
{
    int i = blockIdx.x * blockDim.x + threadIdx.x;
    if (i < n4) {
        float4 v = in[i];
        __half2 lo = __floats2half2_rn(v.x, v.y);
        __half2 hi = __floats2half2_rn(v.z, v.w);
        uint2 o;
        o.x = *reinterpret_cast<uint32_t*>(&lo);
        o.y = *reinterpret_cast<uint32_t*>(&hi);
        out[i] = o;
    }
}

// ---------------------------------------------------------------------------
// Kernel 1: fused triple GEMM (fp16 mma.sync) + activation epilogue
//  CTA tile: BM=128 x BN=64 (per matrix, x3), BK=32, 4-stage cp.async.
//  8 warps (4 along M, 2 along N); warp tile 32x32 per matrix.
//  smem stage: A 128x(32+8)halfs = 10240B ; B 3 x 64x40 halfs = 15360B
// ---------------------------------------------------------------------------
#define BK 32
#define NSTAGE 4
#define ASTRB 80                     // bytes per smem row (32 halfs + 8 pad)
#define A_SM_BYTES (128 * ASTRB)     // 10240
#define B_SM_BYTES (64 * ASTRB)      // 5120 per matrix
#define STAGE_BYTES (A_SM_BYTES + 3 * B_SM_BYTES)   // 25600
#define GEMM_SMEM (NSTAGE * STAGE_BYTES)            // 102400

extern __shared__ char gemm_smem[];

__device__ __forceinline__ void issue_stage(const __half* __restrict__ xh,
                                            const __half* __restrict__ wh,
                                            int m0, int n0, int k0,
                                            uint32_t smbase, int s, int tid)
{
    const uint32_t stg = smbase + (uint32_t)s * STAGE_BYTES;
    // A tile: 128 rows x 64B = 512 x 16B chunks (2 per thread)
    #pragma unroll
    for (int t = 0; t < 2; t++) {
        const int c   = tid + t * 256;
        const int row = c >> 2, kc = c & 3;
        cp_async16(stg + row * ASTRB + kc * 16,
                   xh + (size_t)(m0 + row) * Ddim + k0 + kc * 8);
    }
    // B tiles: 3 x 64 rows x 64B = 768 x 16B chunks (3 per thread)
    #pragma unroll
    for (int t = 0; t < 3; t++) {
        const int c   = tid + t * 256;
        const int mat = c >> 8;
        const int cc  = c & 255;
        const int row = cc >> 2, kc = cc & 3;
        cp_async16(stg + A_SM_BYTES + mat * B_SM_BYTES + row * ASTRB + kc * 16,
                   wh + (size_t)mat * (Ddim * Ddim) +
                        (size_t)(n0 + row) * Ddim + k0 + kc * 8);
    }
}

__global__ __launch_bounds__(256, 1)
void gemm3_fp16_kernel(const __half* __restrict__ xh,
                       const __half* __restrict__ wh,
                       const float* __restrict__ bg,
                       const float* __restrict__ bv,
                       const float* __restrict__ bd)
{
    const int tid  = threadIdx.x;
    const int lane = tid & 31;
    const int wid  = tid >> 5;
    const int m0   = blockIdx.x * 128;
    const int n0   = blockIdx.y * 64;
    const int wm   = (wid & 3) * 32;     // warp M origin
    const int wn   = (wid >> 2) * 32;    // warp N origin
    const int grp  = lane >> 2;          // 0..7
    const int tg   = lane & 3;           // 0..3

    const uint32_t smbase = smem_u32(gemm_smem);
    char* smc = gemm_smem;

    float acc[3][2][4][4];
    #pragma unroll
    for (int w = 0; w < 3; w++)
        #pragma unroll
        for (int mi = 0; mi < 2; mi++)
            #pragma unroll
            for (int ni = 0; ni < 4; ni++)
                #pragma unroll
                for (int r = 0; r < 4; r++) acc[w][mi][ni][r] = 0.0f;

    // prologue: fill 3 stages
    #pragma unroll
    for (int s = 0; s < NSTAGE - 1; s++) {
        issue_stage(xh, wh, m0, n0, s * BK, smbase, s, tid);
        CP_COMMIT();
    }

    const int NITER = Ddim / BK;   // 32
    for (int it = 0; it < NITER; it++) {
        CP_WAIT2();
        __syncthreads();

        if (it + NSTAGE - 1 < NITER)
            issue_stage(xh, wh, m0, n0, (it + NSTAGE - 1) * BK,
                        smbase, (it + NSTAGE - 1) & (NSTAGE - 1), tid);
        CP_COMMIT();

        const uint32_t stg = (uint32_t)(it & (NSTAGE - 1)) * STAGE_BYTES;
        #pragma unroll
        for (int ks = 0; ks < 2; ks++) {
            uint32_t afrag[2][4];
            #pragma unroll
            for (int mi = 0; mi < 2; mi++) {
                const uint32_t ab = stg + (wm + mi * 16 + grp) * ASTRB + ks * 32 + tg * 4;
                afrag[mi][0] = *(const uint32_t*)(smc + ab);
                afrag[mi][1] = *(const uint32_t*)(smc + ab + 8 * ASTRB);
                afrag[mi][2] = *(const uint32_t*)(smc + ab + 16);
                afrag[mi][3] = *(const uint32_t*)(smc + ab + 8 * ASTRB + 16);
            }
            #pragma unroll
            for (int mat = 0; mat < 3; mat++) {
                #pragma unroll
                for (int ni = 0; ni < 4; ni++) {
                    const uint32_t bb = stg + A_SM_BYTES + mat * B_SM_BYTES +
                                        (wn + ni * 8 + grp) * ASTRB + ks * 32 + tg * 4;
                    const uint32_t b0 = *(const uint32_t*)(smc + bb);
                    const uint32_t b1 = *(const uint32_t*)(smc + bb + 16);
                    mma_fp16(acc[mat][0][ni], afrag[0], b0, b1);
                    mma_fp16(acc[mat][1][ni], afrag[1], b0, b1);
                }
            }
        }
        __syncthreads();
    }

    // epilogue: bias + activations -> g_xs, g_a
    #pragma unroll
    for (int mi = 0; mi < 2; mi++) {
        const int rbase = m0 + wm + mi * 16 + grp;
        #pragma unroll
        for (int ni = 0; ni < 4; ni++) {
            const int cc = n0 + wn + ni * 8 + tg * 2;
            const float bg0 = bg[cc], bg1 = bg[cc + 1];
            const float bv0 = bv[cc], bv1 = bv[cc + 1];
            const float bd0 = bd[cc], bd1 = bd[cc + 1];
            #pragma unroll
            for (int rr = 0; rr < 2; rr++) {
                const int row = rbase + rr * 8;
                const float gg0 = acc[0][mi][ni][rr * 2 + 0] + bg0;
                const float gg1 = acc[0][mi][ni][rr * 2 + 1] + bg1;
                const float vv0 = acc[1][mi][ni][rr * 2 + 0] + bv0;
                const float vv1 = acc[1][mi][ni][rr * 2 + 1] + bv1;
                const float dd0 = acc[2][mi][ni][rr * 2 + 0] + bd0;
                const float dd1 = acc[2][mi][ni][rr * 2 + 1] + bd1;

                const float xs0 = sigmoidf_(gg0) * tanhf_(vv0);
                const float xs1 = sigmoidf_(gg1) * tanhf_(vv1);
                const float aa0 = 0.001f + 0.998f * sigmoidf_(dd0);
                const float aa1 = 0.001f + 0.998f * sigmoidf_(dd1);

                const size_t off = (size_t)row * Ddim + cc;
                *(float2*)(g_xs + off) = make_float2(xs0, xs1);
                *(float2*)(g_a  + off) = make_float2(aa0, aa1);
            }
        }
    }
}

// ---------------------------------------------------------------------------
// Kernel 2: per-(channel, chunk): P = prod(a), L = local scan end
// ---------------------------------------------------------------------------
__global__ void chunk_stats_kernel()
{
    const int t = blockIdx.x * blockDim.x + threadIdx.x;
    const int ch    = t & (NCH - 1);
    const int chunk = t >> 12;
    const int b = ch >> 10;
    const int d = ch & (Ddim - 1);
    const size_t base = ((size_t)b * Sdim + (size_t)chunk * CHUNK) * Ddim + d;

    float P = 1.0f, L = 0.0f;
    #pragma unroll 8
    for (int i = 0; i < CHUNK; i++) {
        const float a  = g_a [base + (size_t)i * Ddim];
        const float xv = g_xs[base + (size_t)i * Ddim];
        L = fmaf(a, L, xv);
        P *= a;
    }
    g_P[t] = P;
    g_L[t] = L;
}

// ---------------------------------------------------------------------------
// Kernel 3: sequential carry combine across chunks
// ---------------------------------------------------------------------------
__global__ void carry_kernel()
{
    const int ch = blockIdx.x * blockDim.x + threadIdx.x;
    float h = 0.0f;
    #pragma unroll
    for (int c = 0; c < NCHUNK; c++) {
        g_cin[c * NCH + ch] = h;
        h = fmaf(g_P[c * NCH + ch], h, g_L[c * NCH + ch]);
    }
}

// ---------------------------------------------------------------------------
// Kernel 4: final scan with carry-in
// ---------------------------------------------------------------------------
__global__ void final_scan_kernel(float* __restrict__ out)
{
    const int t = blockIdx.x * blockDim.x + threadIdx.x;
    const int ch    = t & (NCH - 1);
    const int chunk = t >> 12;
    const int b = ch >> 10;
    const int d = ch & (Ddim - 1);
    const size_t base = ((size_t)b * Sdim + (size_t)chunk * CHUNK) * Ddim + d;

    float h = g_cin[t];
    #pragma unroll 8
    for (int i = 0; i < CHUNK; i++) {
        const size_t off = base + (size_t)i * Ddim;
        h = fmaf(g_a[off], h, g_xs[off]);
        out[off] = h;
    }
}

// ---------------------------------------------------------------------------
// Host
// ---------------------------------------------------------------------------
extern "C" void kernel_launch(void* const* d_in, const int* in_sizes, int n_in,
                              void* d_out, int out_size)
{
    const float* x  = (const float*)d_in[0];
    const float* Wg = (const float*)d_in[1];
    const float* bg = (const float*)d_in[2];
    const float* Wv = (const float*)d_in[3];
    const float* bv = (const float*)d_in[4];
    const float* Wd = (const float*)d_in[5];
    const float* bd = (const float*)d_in[6];
    float* out = (float*)d_out;

    void *p_xh, *p_wh;
    cudaGetSymbolAddress(&p_xh, g_xh);
    cudaGetSymbolAddress(&p_wh, g_wh);
    __half* xh = (__half*)p_xh;
    __half* wh = (__half*)p_wh;

    static bool attr_set = false;
    if (!attr_set) {
        cudaFuncSetAttribute(gemm3_fp16_kernel,
                             cudaFuncAttributeMaxDynamicSharedMemorySize, GEMM_SMEM);
        attr_set = true;
    }

    // 0: fp32 -> fp16
    const int nx4 = Mdim * Ddim / 4;     // 4,194,304
    const int nw4 = Ddim * Ddim / 4;     // 262,144
    f32_to_f16_kernel<<<(nx4 + 255) / 256, 256>>>((const float4*)x,  (uint2*)xh, nx4);
    f32_to_f16_kernel<<<(nw4 + 255) / 256, 256>>>((const float4*)Wg, (uint2*)(wh + 0 * (size_t)Ddim * Ddim), nw4);
    f32_to_f16_kernel<<<(nw4 + 255) / 256, 256>>>((const float4*)Wv, (uint2*)(wh + 1 * (size_t)Ddim * Ddim), nw4);
    f32_to_f16_kernel<<<(nw4 + 255) / 256, 256>>>((const float4*)Wd, (uint2*)(wh + 2 * (size_t)Ddim * Ddim), nw4);

    // 1: fused triple GEMM + activations
    dim3 g1(Mdim / 128, Ddim / 64);      // (128, 16)
    gemm3_fp16_kernel<<<g1, 256, GEMM_SMEM>>>(xh, wh, bg, bv, bd);

    // 2-4: chunked causal scan
    chunk_stats_kernel<<<(NCHUNK * NCH) / 256, 256>>>();
    carry_kernel<<<NCH / 256, 256>>>();
    final_scan_kernel<<<(NCHUNK * NCH) / 256, 256>>>(out);
}

// round 5
// speedup vs baseline: 2.5393x; 1.2773x over previous
#include <cuda_runtime.h>
#include <cuda_fp16.h>
#include <cstdint>
#include <cstddef>

// ===========================================================================
// MinGRU B=4 S=4096 D=1024. Round 5:
//  - fp16 mma.sync triple GEMM, ldmatrix.x4 fragment feeds
//  - 3-stage cp.async pipeline, 2 CTAs/SM (__launch_bounds__(256,2))
//  - chunked causal scan unchanged
// ===========================================================================

#define Bdim 4
#define Sdim 4096
#define Ddim 1024
#define Mdim (Bdim * Sdim)        // 16384

#define NCHUNK 32
#define CHUNK  128
#define NCH    (Bdim * Ddim)      // 4096

__device__ float  g_xs[(size_t)Mdim * Ddim];        // 64 MB
__device__ float  g_a [(size_t)Mdim * Ddim];        // 64 MB
__device__ __half g_xh[(size_t)Mdim * Ddim];        // 32 MB
__device__ __half g_wh[(size_t)3 * Ddim * Ddim];    //  6 MB
__device__ float  g_P  [NCHUNK * NCH];
__device__ float  g_L  [NCHUNK * NCH];
__device__ float  g_cin[NCHUNK * NCH];

// ---------------------------------------------------------------------------
__device__ __forceinline__ uint32_t smem_u32(const void* p) {
    uint32_t a;
    asm("{ .reg .u64 t; cvta.to.shared.u64 t, %1; cvt.u32.u64 %0, t; }"
        : "=r"(a) : "l"(p));
    return a;
}

__device__ __forceinline__ void cp_async16(uint32_t dst, const void* src) {
    asm volatile("cp.async.cg.shared.global [%0], [%1], 16;"
                 :: "r"(dst), "l"(src) : "memory");
}
#define CP_COMMIT() asm volatile("cp.async.commit_group;" ::: "memory")
#define CP_WAIT1()  asm volatile("cp.async.wait_group 1;"  ::: "memory")

__device__ __forceinline__ void ldsm_x4(uint32_t* r, uint32_t addr) {
    asm volatile("ldmatrix.sync.aligned.m8n8.x4.shared.b16 {%0,%1,%2,%3}, [%4];"
                 : "=r"(r[0]), "=r"(r[1]), "=r"(r[2]), "=r"(r[3]) : "r"(addr));
}

__device__ __forceinline__ void mma_fp16(float* c, const uint32_t* a,
                                         uint32_t b0, uint32_t b1) {
    asm volatile(
        "mma.sync.aligned.m16n8k16.row.col.f32.f16.f16.f32 "
        "{%0,%1,%2,%3}, {%4,%5,%6,%7}, {%8,%9}, {%0,%1,%2,%3};"
        : "+f"(c[0]), "+f"(c[1]), "+f"(c[2]), "+f"(c[3])
        : "r"(a[0]), "r"(a[1]), "r"(a[2]), "r"(a[3]), "r"(b0), "r"(b1));
}

__device__ __forceinline__ float sigmoidf_(float z) { return 1.0f / (1.0f + __expf(-z)); }
__device__ __forceinline__ float tanhf_(float z)    { return 2.0f / (1.0f + __expf(-2.0f * z)) - 1.0f; }

// ---------------------------------------------------------------------------
// Kernel 0: fp32 -> fp16
// ---------------------------------------------------------------------------
__global__ void f32_to_f16_kernel(const float4* __restrict__ in,
                                  uint2* __restrict__ out, int n4)
{
    int i = blockIdx.x * blockDim.x + threadIdx.x;
    if (i < n4) {
        float4 v = in[i];
        __half2 lo = __floats2half2_rn(v.x, v.y);
        __half2 hi = __floats2half2_rn(v.z, v.w);
        uint2 o;
        o.x = *reinterpret_cast<uint32_t*>(&lo);
        o.y = *reinterpret_cast<uint32_t*>(&hi);
        out[i] = o;
    }
}

// ---------------------------------------------------------------------------
// Kernel 1: fused triple GEMM (fp16 mma.sync + ldmatrix) + activations
//  BM=128, BN=64 (x3 matrices), BK=32, 3-stage cp.async, 2 CTAs/SM.
//  8 warps (4 M x 2 N), warp tile 32x32 per matrix.
// ---------------------------------------------------------------------------
#define BK 32
#define NSTAGE 3
#define ASTRB 80                     // smem row stride bytes (32 halfs + pad)
#define A_SM_BYTES (128 * ASTRB)     // 10240
#define B_SM_BYTES (64 * ASTRB)      // 5120 per matrix
#define STAGE_BYTES (A_SM_BYTES + 3 * B_SM_BYTES)   // 25600
#define GEMM_SMEM (NSTAGE * STAGE_BYTES)            // 76800

extern __shared__ char gemm_smem[];

__device__ __forceinline__ void issue_stage(const __half* __restrict__ xh,
                                            const __half* __restrict__ wh,
                                            int m0, int n0, int k0,
                                            uint32_t smbase, int s, int tid)
{
    const uint32_t stg = smbase + (uint32_t)s * STAGE_BYTES;
    #pragma unroll
    for (int t = 0; t < 2; t++) {
        const int c   = tid + t * 256;
        const int row = c >> 2, kc = c & 3;
        cp_async16(stg + row * ASTRB + kc * 16,
                   xh + (size_t)(m0 + row) * Ddim + k0 + kc * 8);
    }
    #pragma unroll
    for (int t = 0; t < 3; t++) {
        const int c   = tid + t * 256;
        const int mat = c >> 8;
        const int cc  = c & 255;
        const int row = cc >> 2, kc = cc & 3;
        cp_async16(stg + A_SM_BYTES + mat * B_SM_BYTES + row * ASTRB + kc * 16,
                   wh + (size_t)mat * (Ddim * Ddim) +
                        (size_t)(n0 + row) * Ddim + k0 + kc * 8);
    }
}

__global__ __launch_bounds__(256, 2)
void gemm3_fp16_kernel(const __half* __restrict__ xh,
                       const __half* __restrict__ wh,
                       const float* __restrict__ bg,
                       const float* __restrict__ bv,
                       const float* __restrict__ bd)
{
    const int tid  = threadIdx.x;
    const int lane = tid & 31;
    const int wid  = tid >> 5;
    const int m0   = blockIdx.x * 128;
    const int n0   = blockIdx.y * 64;
    const int wm   = (wid & 3) * 32;     // warp M origin
    const int wn   = (wid >> 2) * 32;    // warp N origin
    const int grp  = lane >> 2;
    const int tg   = lane & 3;

    const uint32_t smbase = smem_u32(gemm_smem);

    // ldmatrix per-lane address offsets (within a stage)
    //  A tile (16x16): lanes 0-15 -> row base+(lane&15), k0 ; 16-31 -> k+8
    const uint32_t a_lane_off =
        (uint32_t)((lane & 15) * ASTRB + (lane >> 4) * 16);
    //  B tile-pair (16 n-rows x 16 k): lanes 0-7 row+0 k0 ; 8-15 row+0 k8 ;
    //  16-23 row+8 k0 ; 24-31 row+8 k8
    const uint32_t b_lane_off =
        (uint32_t)(((lane >> 4) * 8 + (lane & 7)) * ASTRB + ((lane >> 3) & 1) * 16);

    float acc[3][2][4][4];
    #pragma unroll
    for (int w = 0; w < 3; w++)
        #pragma unroll
        for (int mi = 0; mi < 2; mi++)
            #pragma unroll
            for (int ni = 0; ni < 4; ni++)
                #pragma unroll
                for (int r = 0; r < 4; r++) acc[w][mi][ni][r] = 0.0f;

    #pragma unroll
    for (int s = 0; s < NSTAGE - 1; s++) {
        issue_stage(xh, wh, m0, n0, s * BK, smbase, s, tid);
        CP_COMMIT();
    }

    const int NITER = Ddim / BK;   // 32
    int slot = 0;
    for (int it = 0; it < NITER; it++) {
        CP_WAIT1();
        __syncthreads();

        const int ns = it + NSTAGE - 1;
        if (ns < NITER) {
            int nslot = slot + (NSTAGE - 1);
            if (nslot >= NSTAGE) nslot -= NSTAGE;
            issue_stage(xh, wh, m0, n0, ns * BK, smbase, nslot, tid);
        }
        CP_COMMIT();

        const uint32_t stg = smbase + (uint32_t)slot * STAGE_BYTES;
        #pragma unroll
        for (int ks = 0; ks < 2; ks++) {
            uint32_t afrag[2][4];
            #pragma unroll
            for (int mi = 0; mi < 2; mi++)
                ldsm_x4(afrag[mi],
                        stg + (wm + mi * 16) * ASTRB + ks * 32 + a_lane_off);
            #pragma unroll
            for (int mat = 0; mat < 3; mat++) {
                #pragma unroll
                for (int np = 0; np < 2; np++) {       // ni pairs {0,1},{2,3}
                    uint32_t bfrag[4];
                    ldsm_x4(bfrag,
                            stg + A_SM_BYTES + mat * B_SM_BYTES +
                            (wn + np * 16) * ASTRB + ks * 32 + b_lane_off);
                    #pragma unroll
                    for (int h = 0; h < 2; h++) {      // ni = np*2 + h
                        mma_fp16(acc[mat][0][np * 2 + h], afrag[0],
                                 bfrag[h * 2], bfrag[h * 2 + 1]);
                        mma_fp16(acc[mat][1][np * 2 + h], afrag[1],
                                 bfrag[h * 2], bfrag[h * 2 + 1]);
                    }
                }
            }
        }
        __syncthreads();
        if (++slot == NSTAGE) slot = 0;
    }

    // epilogue
    #pragma unroll
    for (int mi = 0; mi < 2; mi++) {
        const int rbase = m0 + wm + mi * 16 + grp;
        #pragma unroll
        for (int ni = 0; ni < 4; ni++) {
            const int cc = n0 + wn + ni * 8 + tg * 2;
            const float bg0 = bg[cc], bg1 = bg[cc + 1];
            const float bv0 = bv[cc], bv1 = bv[cc + 1];
            const float bd0 = bd[cc], bd1 = bd[cc + 1];
            #pragma unroll
            for (int rr = 0; rr < 2; rr++) {
                const int row = rbase + rr * 8;
                const float gg0 = acc[0][mi][ni][rr * 2 + 0] + bg0;
                const float gg1 = acc[0][mi][ni][rr * 2 + 1] + bg1;
                const float vv0 = acc[1][mi][ni][rr * 2 + 0] + bv0;
                const float vv1 = acc[1][mi][ni][rr * 2 + 1] + bv1;
                const float dd0 = acc[2][mi][ni][rr * 2 + 0] + bd0;
                const float dd1 = acc[2][mi][ni][rr * 2 + 1] + bd1;

                const float xs0 = sigmoidf_(gg0) * tanhf_(vv0);
                const float xs1 = sigmoidf_(gg1) * tanhf_(vv1);
                const float aa0 = 0.001f + 0.998f * sigmoidf_(dd0);
                const float aa1 = 0.001f + 0.998f * sigmoidf_(dd1);

                const size_t off = (size_t)row * Ddim + cc;
                *(float2*)(g_xs + off) = make_float2(xs0, xs1);
                *(float2*)(g_a  + off) = make_float2(aa0, aa1);
            }
        }
    }
}

// ---------------------------------------------------------------------------
// Kernel 2: per-(channel, chunk): P = prod(a), L = local scan end
// ---------------------------------------------------------------------------
__global__ void chunk_stats_kernel()
{
    const int t = blockIdx.x * blockDim.x + threadIdx.x;
    const int ch    = t & (NCH - 1);
    const int chunk = t >> 12;
    const int b = ch >> 10;
    const int d = ch & (Ddim - 1);
    const size_t base = ((size_t)b * Sdim + (size_t)chunk * CHUNK) * Ddim + d;

    float P = 1.0f, L = 0.0f;
    #pragma unroll 8
    for (int i = 0; i < CHUNK; i++) {
        const float a  = g_a [base + (size_t)i * Ddim];
        const float xv = g_xs[base + (size_t)i * Ddim];
        L = fmaf(a, L, xv);
        P *= a;
    }
    g_P[t] = P;
    g_L[t] = L;
}

// ---------------------------------------------------------------------------
// Kernel 3: sequential carry combine
// ---------------------------------------------------------------------------
__global__ void carry_kernel()
{
    const int ch = blockIdx.x * blockDim.x + threadIdx.x;
    float h = 0.0f;
    #pragma unroll
    for (int c = 0; c < NCHUNK; c++) {
        g_cin[c * NCH + ch] = h;
        h = fmaf(g_P[c * NCH + ch], h, g_L[c * NCH + ch]);
    }
}

// ---------------------------------------------------------------------------
// Kernel 4: final scan with carry-in
// ---------------------------------------------------------------------------
__global__ void final_scan_kernel(float* __restrict__ out)
{
    const int t = blockIdx.x * blockDim.x + threadIdx.x;
    const int ch    = t & (NCH - 1);
    const int chunk = t >> 12;
    const int b = ch >> 10;
    const int d = ch & (Ddim - 1);
    const size_t base = ((size_t)b * Sdim + (size_t)chunk * CHUNK) * Ddim + d;

    float h = g_cin[t];
    #pragma unroll 8
    for (int i = 0; i < CHUNK; i++) {
        const size_t off = base + (size_t)i * Ddim;
        h = fmaf(g_a[off], h, g_xs[off]);
        out[off] = h;
    }
}

// ---------------------------------------------------------------------------
// Host
// ---------------------------------------------------------------------------
extern "C" void kernel_launch(void* const* d_in, const int* in_sizes, int n_in,
                              void* d_out, int out_size)
{
    const float* x  = (const float*)d_in[0];
    const float* Wg = (const float*)d_in[1];
    const float* bg = (const float*)d_in[2];
    const float* Wv = (const float*)d_in[3];
    const float* bv = (const float*)d_in[4];
    const float* Wd = (const float*)d_in[5];
    const float* bd = (const float*)d_in[6];
    float* out = (float*)d_out;

    void *p_xh, *p_wh;
    cudaGetSymbolAddress(&p_xh, g_xh);
    cudaGetSymbolAddress(&p_wh, g_wh);
    __half* xh = (__half*)p_xh;
    __half* wh = (__half*)p_wh;

    static bool attr_set = false;
    if (!attr_set) {
        cudaFuncSetAttribute(gemm3_fp16_kernel,
                             cudaFuncAttributeMaxDynamicSharedMemorySize, GEMM_SMEM);
        attr_set = true;
    }

    const int nx4 = Mdim * Ddim / 4;
    const int nw4 = Ddim * Ddim / 4;
    f32_to_f16_kernel<<<(nx4 + 255) / 256, 256>>>((const float4*)x,  (uint2*)xh, nx4);
    f32_to_f16_kernel<<<(nw4 + 255) / 256, 256>>>((const float4*)Wg, (uint2*)(wh + 0 * (size_t)Ddim * Ddim), nw4);
    f32_to_f16_kernel<<<(nw4 + 255) / 256, 256>>>((const float4*)Wv, (uint2*)(wh + 1 * (size_t)Ddim * Ddim), nw4);
    f32_to_f16_kernel<<<(nw4 + 255) / 256, 256>>>((const float4*)Wd, (uint2*)(wh + 2 * (size_t)Ddim * Ddim), nw4);

    dim3 g1(Mdim / 128, Ddim / 64);      // (128, 16)
    gemm3_fp16_kernel<<<g1, 256, GEMM_SMEM>>>(xh, wh, bg, bv, bd);

    chunk_stats_kernel<<<(NCHUNK * NCH) / 256, 256>>>();
    carry_kernel<<<NCH / 256, 256>>>();
    final_scan_kernel<<<(NCHUNK * NCH) / 256, 256>>>(out);
}

// round 9
// speedup vs baseline: 2.5549x; 1.0061x over previous
#include <cuda_runtime.h>
#include <cuda_fp16.h>
#include <cstdint>
#include <cstddef>

// ===========================================================================
// MinGRU B=4 S=4096 D=1024. Round 6:
//  - fp16 mma.sync triple GEMM (at legacy-HMMA rate floor, ~512 MACs/cyc/SM)
//  - chunk_stats FUSED into GEMM epilogue via smem (CTA tile == scan chunk)
//  - xs stored fp16 (a stays fp32), W converts merged into one launch
// ===========================================================================

#define Bdim 4
#define Sdim 4096
#define Ddim 1024
#define Mdim (Bdim * Sdim)        // 16384

#define NCHUNK 32
#define CHUNK  128
#define NCH    (Bdim * Ddim)      // 4096

__device__ float  g_a  [(size_t)Mdim * Ddim];       // 64 MB
__device__ __half g_xsh[(size_t)Mdim * Ddim];       // 32 MB (fp16 x_scan)
__device__ __half g_xh [(size_t)Mdim * Ddim];       // 32 MB (fp16 x)
__device__ __half g_wh [(size_t)3 * Ddim * Ddim];   //  6 MB (fp16 W)
__device__ float  g_P  [NCHUNK * NCH];
__device__ float  g_L  [NCHUNK * NCH];
__device__ float  g_cin[NCHUNK * NCH];

// ---------------------------------------------------------------------------
__device__ __forceinline__ uint32_t smem_u32(const void* p) {
    uint32_t a;
    asm("{ .reg .u64 t; cvta.to.shared.u64 t, %1; cvt.u32.u64 %0, t; }"
        : "=r"(a) : "l"(p));
    return a;
}

__device__ __forceinline__ void cp_async16(uint32_t dst, const void* src) {
    asm volatile("cp.async.cg.shared.global [%0], [%1], 16;"
                 :: "r"(dst), "l"(src) : "memory");
}
#define CP_COMMIT() asm volatile("cp.async.commit_group;" ::: "memory")
#define CP_WAIT1()  asm volatile("cp.async.wait_group 1;"  ::: "memory")

__device__ __forceinline__ void ldsm_x4(uint32_t* r, uint32_t addr) {
    asm volatile("ldmatrix.sync.aligned.m8n8.x4.shared.b16 {%0,%1,%2,%3}, [%4];"
                 : "=r"(r[0]), "=r"(r[1]), "=r"(r[2]), "=r"(r[3]) : "r"(addr));
}

__device__ __forceinline__ void mma_fp16(float* c, const uint32_t* a,
                                         uint32_t b0, uint32_t b1) {
    asm volatile(
        "mma.sync.aligned.m16n8k16.row.col.f32.f16.f16.f32 "
        "{%0,%1,%2,%3}, {%4,%5,%6,%7}, {%8,%9}, {%0,%1,%2,%3};"
        : "+f"(c[0]), "+f"(c[1]), "+f"(c[2]), "+f"(c[3])
        : "r"(a[0]), "r"(a[1]), "r"(a[2]), "r"(a[3]), "r"(b0), "r"(b1));
}

__device__ __forceinline__ float sigmoidf_(float z) { return 1.0f / (1.0f + __expf(-z)); }
__device__ __forceinline__ float tanhf_(float z)    { return 2.0f / (1.0f + __expf(-2.0f * z)) - 1.0f; }

// ---------------------------------------------------------------------------
// Kernel 0a: x fp32 -> fp16
// ---------------------------------------------------------------------------
__global__ void f32_to_f16_kernel(const float4* __restrict__ in,
                                  uint2* __restrict__ out, int n4)
{
    int i = blockIdx.x * blockDim.x + threadIdx.x;
    if (i < n4) {
        float4 v = in[i];
        __half2 lo = __floats2half2_rn(v.x, v.y);
        __half2 hi = __floats2half2_rn(v.z, v.w);
        uint2 o;
        o.x = *reinterpret_cast<uint32_t*>(&lo);
        o.y = *reinterpret_cast<uint32_t*>(&hi);
        out[i] = o;
    }
}

// Kernel 0b: all three W matrices in one launch
__global__ void w_to_f16_kernel(const float4* __restrict__ w0,
                                const float4* __restrict__ w1,
                                const float4* __restrict__ w2,
                                uint2* __restrict__ out, int n4each)
{
    int i = blockIdx.x * blockDim.x + threadIdx.x;   // 0 .. 3*n4each-1
    const int mat = i / n4each;
    const int j   = i - mat * n4each;
    const float4* src = (mat == 0) ? w0 : (mat == 1) ? w1 : w2;
    float4 v = src[j];
    __half2 lo = __floats2half2_rn(v.x, v.y);
    __half2 hi = __floats2half2_rn(v.z, v.w);
    uint2 o;
    o.x = *reinterpret_cast<uint32_t*>(&lo);
    o.y = *reinterpret_cast<uint32_t*>(&hi);
    out[i] = o;
}

// ---------------------------------------------------------------------------
// Kernel 1: fused triple GEMM + activations + per-chunk scan stats
//  BM=128 (== one scan chunk), BN=64, BK=32, 3-stage cp.async, 2 CTAs/SM.
// ---------------------------------------------------------------------------
#define BK 32
#define NSTAGE 3
#define ASTRB 80
#define A_SM_BYTES (128 * ASTRB)                    // 10240
#define B_SM_BYTES (64 * ASTRB)                     // 5120
#define STAGE_BYTES (A_SM_BYTES + 3 * B_SM_BYTES)   // 25600
#define GEMM_SMEM (NSTAGE * STAGE_BYTES)            // 76800
#define EPI_STR 66                                  // floats per smem row

extern __shared__ char gemm_smem[];

__device__ __forceinline__ void issue_stage(const __half* __restrict__ xh,
                                            const __half* __restrict__ wh,
                                            int m0, int n0, int k0,
                                            uint32_t smbase, int s, int tid)
{
    const uint32_t stg = smbase + (uint32_t)s * STAGE_BYTES;
    #pragma unroll
    for (int t = 0; t < 2; t++) {
        const int c   = tid + t * 256;
        const int row = c >> 2, kc = c & 3;
        cp_async16(stg + row * ASTRB + kc * 16,
                   xh + (size_t)(m0 + row) * Ddim + k0 + kc * 8);
    }
    #pragma unroll
    for (int t = 0; t < 3; t++) {
        const int c   = tid + t * 256;
        const int mat = c >> 8;
        const int cc  = c & 255;
        const int row = cc >> 2, kc = cc & 3;
        cp_async16(stg + A_SM_BYTES + mat * B_SM_BYTES + row * ASTRB + kc * 16,
                   wh + (size_t)mat * (Ddim * Ddim) +
                        (size_t)(n0 + row) * Ddim + k0 + kc * 8);
    }
}

__global__ __launch_bounds__(256, 2)
void gemm3_fp16_kernel(const __half* __restrict__ xh,
                       const __half* __restrict__ wh,
                       const float* __restrict__ bg,
                       const float* __restrict__ bv,
                       const float* __restrict__ bd)
{
    const int tid  = threadIdx.x;
    const int lane = tid & 31;
    const int wid  = tid >> 5;
    const int m0   = blockIdx.x * 128;
    const int n0   = blockIdx.y * 64;
    const int wm   = (wid & 3) * 32;
    const int wn   = (wid >> 2) * 32;
    const int grp  = lane >> 2;
    const int tg   = lane & 3;

    const uint32_t smbase = smem_u32(gemm_smem);

    const uint32_t a_lane_off =
        (uint32_t)((lane & 15) * ASTRB + (lane >> 4) * 16);
    const uint32_t b_lane_off =
        (uint32_t)(((lane >> 4) * 8 + (lane & 7)) * ASTRB + ((lane >> 3) & 1) * 16);

    float acc[3][2][4][4];
    #pragma unroll
    for (int w = 0; w < 3; w++)
        #pragma unroll
        for (int mi = 0; mi < 2; mi++)
            #pragma unroll
            for (int ni = 0; ni < 4; ni++)
                #pragma unroll
                for (int r = 0; r < 4; r++) acc[w][mi][ni][r] = 0.0f;

    #pragma unroll
    for (int s = 0; s < NSTAGE - 1; s++) {
        issue_stage(xh, wh, m0, n0, s * BK, smbase, s, tid);
        CP_COMMIT();
    }

    const int NITER = Ddim / BK;   // 32
    int slot = 0;
    for (int it = 0; it < NITER; it++) {
        CP_WAIT1();
        __syncthreads();

        const int ns = it + NSTAGE - 1;
        if (ns < NITER) {
            int nslot = slot + (NSTAGE - 1);
            if (nslot >= NSTAGE) nslot -= NSTAGE;
            issue_stage(xh, wh, m0, n0, ns * BK, smbase, nslot, tid);
        }
        CP_COMMIT();

        const uint32_t stg = smbase + (uint32_t)slot * STAGE_BYTES;
        #pragma unroll
        for (int ks = 0; ks < 2; ks++) {
            uint32_t afrag[2][4];
            #pragma unroll
            for (int mi = 0; mi < 2; mi++)
                ldsm_x4(afrag[mi],
                        stg + (wm + mi * 16) * ASTRB + ks * 32 + a_lane_off);
            #pragma unroll
            for (int mat = 0; mat < 3; mat++) {
                #pragma unroll
                for (int np = 0; np < 2; np++) {
                    uint32_t bfrag[4];
                    ldsm_x4(bfrag,
                            stg + A_SM_BYTES + mat * B_SM_BYTES +
                            (wn + np * 16) * ASTRB + ks * 32 + b_lane_off);
                    #pragma unroll
                    for (int h = 0; h < 2; h++) {
                        mma_fp16(acc[mat][0][np * 2 + h], afrag[0],
                                 bfrag[h * 2], bfrag[h * 2 + 1]);
                        mma_fp16(acc[mat][1][np * 2 + h], afrag[1],
                                 bfrag[h * 2], bfrag[h * 2 + 1]);
                    }
                }
            }
        }
        __syncthreads();
        if (++slot == NSTAGE) slot = 0;
    }

    // ---- epilogue: bias+activations -> gmem (xs fp16, a fp32) + smem stage
    float* xs_sm = (float*)gemm_smem;                 // [128][EPI_STR]
    float* a_sm  = xs_sm + 128 * EPI_STR;             // [128][EPI_STR]

    #pragma unroll
    for (int mi = 0; mi < 2; mi++) {
        const int rl = wm + mi * 16 + grp;            // local row (time within chunk)
        #pragma unroll
        for (int ni = 0; ni < 4; ni++) {
            const int cl = wn + ni * 8 + tg * 2;      // local col (channel)
            const int cc = n0 + cl;
            const float bg0 = bg[cc], bg1 = bg[cc + 1];
            const float bv0 = bv[cc], bv1 = bv[cc + 1];
            const float bd0 = bd[cc], bd1 = bd[cc + 1];
            #pragma unroll
            for (int rr = 0; rr < 2; rr++) {
                const int rloc = rl + rr * 8;
                const int row  = m0 + rloc;
                const float gg0 = acc[0][mi][ni][rr * 2 + 0] + bg0;
                const float gg1 = acc[0][mi][ni][rr * 2 + 1] + bg1;
                const float vv0 = acc[1][mi][ni][rr * 2 + 0] + bv0;
                const float vv1 = acc[1][mi][ni][rr * 2 + 1] + bv1;
                const float dd0 = acc[2][mi][ni][rr * 2 + 0] + bd0;
                const float dd1 = acc[2][mi][ni][rr * 2 + 1] + bd1;

                const float xs0 = sigmoidf_(gg0) * tanhf_(vv0);
                const float xs1 = sigmoidf_(gg1) * tanhf_(vv1);
                const float aa0 = 0.001f + 0.998f * sigmoidf_(dd0);
                const float aa1 = 0.001f + 0.998f * sigmoidf_(dd1);

                const size_t off = (size_t)row * Ddim + cc;
                *(__half2*)(g_xsh + off) = __floats2half2_rn(xs0, xs1);
                *(float2*)(g_a + off)    = make_float2(aa0, aa1);

                xs_sm[rloc * EPI_STR + cl]     = xs0;
                xs_sm[rloc * EPI_STR + cl + 1] = xs1;
                a_sm [rloc * EPI_STR + cl]     = aa0;
                a_sm [rloc * EPI_STR + cl + 1] = aa1;
            }
        }
    }
    __syncthreads();

    // ---- fused chunk stats: P = prod(a), L = local scan end, per channel
    if (tid < 64) {
        float P = 1.0f, L = 0.0f;
        #pragma unroll 8
        for (int t = 0; t < CHUNK; t++) {
            const float a  = a_sm [t * EPI_STR + tid];
            const float xv = xs_sm[t * EPI_STR + tid];
            L = fmaf(a, L, xv);
            P *= a;
        }
        const int b     = blockIdx.x >> 5;            // batch
        const int chunk = blockIdx.x & 31;            // time chunk
        const int gi    = chunk * NCH + b * Ddim + n0 + tid;
        g_P[gi] = P;
        g_L[gi] = L;
    }
}

// ---------------------------------------------------------------------------
// Kernel 3: sequential carry combine across chunks
// ---------------------------------------------------------------------------
__global__ void carry_kernel()
{
    const int ch = blockIdx.x * blockDim.x + threadIdx.x;
    float h = 0.0f;
    #pragma unroll
    for (int c = 0; c < NCHUNK; c++) {
        g_cin[c * NCH + ch] = h;
        h = fmaf(g_P[c * NCH + ch], h, g_L[c * NCH + ch]);
    }
}

// ---------------------------------------------------------------------------
// Kernel 4: final scan with carry-in (xs fp16, a fp32)
// ---------------------------------------------------------------------------
__global__ void final_scan_kernel(float* __restrict__ out)
{
    const int t = blockIdx.x * blockDim.x + threadIdx.x;
    const int ch    = t & (NCH - 1);
    const int chunk = t >> 12;
    const int b = ch >> 10;
    const int d = ch & (Ddim - 1);
    const size_t base = ((size_t)b * Sdim + (size_t)chunk * CHUNK) * Ddim + d;

    float h = g_cin[t];
    #pragma unroll 8
    for (int i = 0; i < CHUNK; i++) {
        const size_t off = base + (size_t)i * Ddim;
        h = fmaf(g_a[off], h, __half2float(g_xsh[off]));
        out[off] = h;
    }
}

// ---------------------------------------------------------------------------
// Host
// ---------------------------------------------------------------------------
extern "C" void kernel_launch(void* const* d_in, const int* in_sizes, int n_in,
                              void* d_out, int out_size)
{
    const float* x  = (const float*)d_in[0];
    const float* Wg = (const float*)d_in[1];
    const float* bg = (const float*)d_in[2];
    const float* Wv = (const float*)d_in[3];
    const float* bv = (const float*)d_in[4];
    const float* Wd = (const float*)d_in[5];
    const float* bd = (const float*)d_in[6];
    float* out = (float*)d_out;

    void *p_xh, *p_wh;
    cudaGetSymbolAddress(&p_xh, g_xh);
    cudaGetSymbolAddress(&p_wh, g_wh);
    __half* xh = (__half*)p_xh;
    __half* wh = (__half*)p_wh;

    static bool attr_set = false;
    if (!attr_set) {
        cudaFuncSetAttribute(gemm3_fp16_kernel,
                             cudaFuncAttributeMaxDynamicSharedMemorySize, GEMM_SMEM);
        attr_set = true;
    }

    const int nx4 = Mdim * Ddim / 4;     // 4,194,304
    const int nw4 = Ddim * Ddim / 4;     // 262,144
    f32_to_f16_kernel<<<(nx4 + 255) / 256, 256>>>((const float4*)x, (uint2*)xh, nx4);
    w_to_f16_kernel<<<(3 * nw4) / 256, 256>>>((const float4*)Wg, (const float4*)Wv,
                                              (const float4*)Wd, (uint2*)wh, nw4);

    dim3 g1(Mdim / 128, Ddim / 64);      // (128, 16)
    gemm3_fp16_kernel<<<g1, 256, GEMM_SMEM>>>(xh, wh, bg, bv, bd);

    carry_kernel<<<NCH / 256, 256>>>();
    final_scan_kernel<<<(NCHUNK * NCH) / 256, 256>>>(out);
}

// round 10
// speedup vs baseline: 2.6640x; 1.0427x over previous
#include <cuda_runtime.h>
#include <cuda_fp16.h>
#include <cstdint>
#include <cstddef>

// ===========================================================================
// MinGRU B=4 S=4096 D=1024. Round 10:
//  - fp16 mma.sync triple GEMM (at legacy-HMMA rate floor) + fused chunk stats
//  - a AND xs stored fp16 (stats computed from rounded values for consistency)
//  - carry kernel: prefetch all P/L (MLP=64) then register FMA chain
//  - final_scan: half2 (2 channels/thread)
// ===========================================================================

#define Bdim 4
#define Sdim 4096
#define Ddim 1024
#define Mdim (Bdim * Sdim)        // 16384

#define NCHUNK 32
#define CHUNK  128
#define NCH    (Bdim * Ddim)      // 4096

__device__ __half g_ah [(size_t)Mdim * Ddim];       // 32 MB (fp16 a)
__device__ __half g_xsh[(size_t)Mdim * Ddim];       // 32 MB (fp16 x_scan)
__device__ __half g_xh [(size_t)Mdim * Ddim];       // 32 MB (fp16 x)
__device__ __half g_wh [(size_t)3 * Ddim * Ddim];   //  6 MB (fp16 W)
__device__ float  g_P  [NCHUNK * NCH];
__device__ float  g_L  [NCHUNK * NCH];
__device__ float  g_cin[NCHUNK * NCH];

// ---------------------------------------------------------------------------
__device__ __forceinline__ uint32_t smem_u32(const void* p) {
    uint32_t a;
    asm("{ .reg .u64 t; cvta.to.shared.u64 t, %1; cvt.u32.u64 %0, t; }"
        : "=r"(a) : "l"(p));
    return a;
}

__device__ __forceinline__ void cp_async16(uint32_t dst, const void* src) {
    asm volatile("cp.async.cg.shared.global [%0], [%1], 16;"
                 :: "r"(dst), "l"(src) : "memory");
}
#define CP_COMMIT() asm volatile("cp.async.commit_group;" ::: "memory")
#define CP_WAIT1()  asm volatile("cp.async.wait_group 1;"  ::: "memory")

__device__ __forceinline__ void ldsm_x4(uint32_t* r, uint32_t addr) {
    asm volatile("ldmatrix.sync.aligned.m8n8.x4.shared.b16 {%0,%1,%2,%3}, [%4];"
                 : "=r"(r[0]), "=r"(r[1]), "=r"(r[2]), "=r"(r[3]) : "r"(addr));
}

__device__ __forceinline__ void mma_fp16(float* c, const uint32_t* a,
                                         uint32_t b0, uint32_t b1) {
    asm volatile(
        "mma.sync.aligned.m16n8k16.row.col.f32.f16.f16.f32 "
        "{%0,%1,%2,%3}, {%4,%5,%6,%7}, {%8,%9}, {%0,%1,%2,%3};"
        : "+f"(c[0]), "+f"(c[1]), "+f"(c[2]), "+f"(c[3])
        : "r"(a[0]), "r"(a[1]), "r"(a[2]), "r"(a[3]), "r"(b0), "r"(b1));
}

__device__ __forceinline__ float sigmoidf_(float z) { return 1.0f / (1.0f + __expf(-z)); }
__device__ __forceinline__ float tanhf_(float z)    { return 2.0f / (1.0f + __expf(-2.0f * z)) - 1.0f; }

// ---------------------------------------------------------------------------
// Kernel 0a: x fp32 -> fp16
// ---------------------------------------------------------------------------
__global__ void f32_to_f16_kernel(const float4* __restrict__ in,
                                  uint2* __restrict__ out, int n4)
{
    int i = blockIdx.x * blockDim.x + threadIdx.x;
    if (i < n4) {
        float4 v = in[i];
        __half2 lo = __floats2half2_rn(v.x, v.y);
        __half2 hi = __floats2half2_rn(v.z, v.w);
        uint2 o;
        o.x = *reinterpret_cast<uint32_t*>(&lo);
        o.y = *reinterpret_cast<uint32_t*>(&hi);
        out[i] = o;
    }
}

// Kernel 0b: all three W matrices in one launch
__global__ void w_to_f16_kernel(const float4* __restrict__ w0,
                                const float4* __restrict__ w1,
                                const float4* __restrict__ w2,
                                uint2* __restrict__ out, int n4each)
{
    int i = blockIdx.x * blockDim.x + threadIdx.x;
    const int mat = i / n4each;
    const int j   = i - mat * n4each;
    const float4* src = (mat == 0) ? w0 : (mat == 1) ? w1 : w2;
    float4 v = src[j];
    __half2 lo = __floats2half2_rn(v.x, v.y);
    __half2 hi = __floats2half2_rn(v.z, v.w);
    uint2 o;
    o.x = *reinterpret_cast<uint32_t*>(&lo);
    o.y = *reinterpret_cast<uint32_t*>(&hi);
    out[i] = o;
}

// ---------------------------------------------------------------------------
// Kernel 1: fused triple GEMM + activations + per-chunk scan stats
//  BM=128 (== one scan chunk), BN=64, BK=32, 3-stage cp.async, 2 CTAs/SM.
// ---------------------------------------------------------------------------
#define BK 32
#define NSTAGE 3
#define ASTRB 80
#define A_SM_BYTES (128 * ASTRB)                    // 10240
#define B_SM_BYTES (64 * ASTRB)                     // 5120
#define STAGE_BYTES (A_SM_BYTES + 3 * B_SM_BYTES)   // 25600
#define GEMM_SMEM (NSTAGE * STAGE_BYTES)            // 76800
#define EPI_STR 66

extern __shared__ char gemm_smem[];

__device__ __forceinline__ void issue_stage(const __half* __restrict__ xh,
                                            const __half* __restrict__ wh,
                                            int m0, int n0, int k0,
                                            uint32_t smbase, int s, int tid)
{
    const uint32_t stg = smbase + (uint32_t)s * STAGE_BYTES;
    #pragma unroll
    for (int t = 0; t < 2; t++) {
        const int c   = tid + t * 256;
        const int row = c >> 2, kc = c & 3;
        cp_async16(stg + row * ASTRB + kc * 16,
                   xh + (size_t)(m0 + row) * Ddim + k0 + kc * 8);
    }
    #pragma unroll
    for (int t = 0; t < 3; t++) {
        const int c   = tid + t * 256;
        const int mat = c >> 8;
        const int cc  = c & 255;
        const int row = cc >> 2, kc = cc & 3;
        cp_async16(stg + A_SM_BYTES + mat * B_SM_BYTES + row * ASTRB + kc * 16,
                   wh + (size_t)mat * (Ddim * Ddim) +
                        (size_t)(n0 + row) * Ddim + k0 + kc * 8);
    }
}

__global__ __launch_bounds__(256, 2)
void gemm3_fp16_kernel(const __half* __restrict__ xh,
                       const __half* __restrict__ wh,
                       const float* __restrict__ bg,
                       const float* __restrict__ bv,
                       const float* __restrict__ bd)
{
    const int tid  = threadIdx.x;
    const int lane = tid & 31;
    const int wid  = tid >> 5;
    const int m0   = blockIdx.x * 128;
    const int n0   = blockIdx.y * 64;
    const int wm   = (wid & 3) * 32;
    const int wn   = (wid >> 2) * 32;
    const int grp  = lane >> 2;
    const int tg   = lane & 3;

    const uint32_t smbase = smem_u32(gemm_smem);

    const uint32_t a_lane_off =
        (uint32_t)((lane & 15) * ASTRB + (lane >> 4) * 16);
    const uint32_t b_lane_off =
        (uint32_t)(((lane >> 4) * 8 + (lane & 7)) * ASTRB + ((lane >> 3) & 1) * 16);

    float acc[3][2][4][4];
    #pragma unroll
    for (int w = 0; w < 3; w++)
        #pragma unroll
        for (int mi = 0; mi < 2; mi++)
            #pragma unroll
            for (int ni = 0; ni < 4; ni++)
                #pragma unroll
                for (int r = 0; r < 4; r++) acc[w][mi][ni][r] = 0.0f;

    #pragma unroll
    for (int s = 0; s < NSTAGE - 1; s++) {
        issue_stage(xh, wh, m0, n0, s * BK, smbase, s, tid);
        CP_COMMIT();
    }

    const int NITER = Ddim / BK;   // 32
    int slot = 0;
    for (int it = 0; it < NITER; it++) {
        CP_WAIT1();
        __syncthreads();

        const int ns = it + NSTAGE - 1;
        if (ns < NITER) {
            int nslot = slot + (NSTAGE - 1);
            if (nslot >= NSTAGE) nslot -= NSTAGE;
            issue_stage(xh, wh, m0, n0, ns * BK, smbase, nslot, tid);
        }
        CP_COMMIT();

        const uint32_t stg = smbase + (uint32_t)slot * STAGE_BYTES;
        #pragma unroll
        for (int ks = 0; ks < 2; ks++) {
            uint32_t afrag[2][4];
            #pragma unroll
            for (int mi = 0; mi < 2; mi++)
                ldsm_x4(afrag[mi],
                        stg + (wm + mi * 16) * ASTRB + ks * 32 + a_lane_off);
            #pragma unroll
            for (int mat = 0; mat < 3; mat++) {
                #pragma unroll
                for (int np = 0; np < 2; np++) {
                    uint32_t bfrag[4];
                    ldsm_x4(bfrag,
                            stg + A_SM_BYTES + mat * B_SM_BYTES +
                            (wn + np * 16) * ASTRB + ks * 32 + b_lane_off);
                    #pragma unroll
                    for (int h = 0; h < 2; h++) {
                        mma_fp16(acc[mat][0][np * 2 + h], afrag[0],
                                 bfrag[h * 2], bfrag[h * 2 + 1]);
                        mma_fp16(acc[mat][1][np * 2 + h], afrag[1],
                                 bfrag[h * 2], bfrag[h * 2 + 1]);
                    }
                }
            }
        }
        __syncthreads();
        if (++slot == NSTAGE) slot = 0;
    }

    // ---- epilogue: bias+activations -> gmem (fp16) + smem stage (rounded)
    float* xs_sm = (float*)gemm_smem;                 // [128][EPI_STR]
    float* a_sm  = xs_sm + 128 * EPI_STR;             // [128][EPI_STR]

    #pragma unroll
    for (int mi = 0; mi < 2; mi++) {
        const int rl = wm + mi * 16 + grp;
        #pragma unroll
        for (int ni = 0; ni < 4; ni++) {
            const int cl = wn + ni * 8 + tg * 2;
            const int cc = n0 + cl;
            const float bg0 = bg[cc], bg1 = bg[cc + 1];
            const float bv0 = bv[cc], bv1 = bv[cc + 1];
            const float bd0 = bd[cc], bd1 = bd[cc + 1];
            #pragma unroll
            for (int rr = 0; rr < 2; rr++) {
                const int rloc = rl + rr * 8;
                const int row  = m0 + rloc;
                const float gg0 = acc[0][mi][ni][rr * 2 + 0] + bg0;
                const float gg1 = acc[0][mi][ni][rr * 2 + 1] + bg1;
                const float vv0 = acc[1][mi][ni][rr * 2 + 0] + bv0;
                const float vv1 = acc[1][mi][ni][rr * 2 + 1] + bv1;
                const float dd0 = acc[2][mi][ni][rr * 2 + 0] + bd0;
                const float dd1 = acc[2][mi][ni][rr * 2 + 1] + bd1;

                const float xs0 = sigmoidf_(gg0) * tanhf_(vv0);
                const float xs1 = sigmoidf_(gg1) * tanhf_(vv1);
                const float aa0 = 0.001f + 0.998f * sigmoidf_(dd0);
                const float aa1 = 0.001f + 0.998f * sigmoidf_(dd1);

                const __half2 xsh2 = __floats2half2_rn(xs0, xs1);
                const __half2 aah2 = __floats2half2_rn(aa0, aa1);
                const size_t off = (size_t)row * Ddim + cc;
                *(__half2*)(g_xsh + off) = xsh2;
                *(__half2*)(g_ah  + off) = aah2;

                // stage the ROUNDED values so P/L match final_scan exactly
                const float2 xsr = __half22float2(xsh2);
                const float2 aar = __half22float2(aah2);
                xs_sm[rloc * EPI_STR + cl]     = xsr.x;
                xs_sm[rloc * EPI_STR + cl + 1] = xsr.y;
                a_sm [rloc * EPI_STR + cl]     = aar.x;
                a_sm [rloc * EPI_STR + cl + 1] = aar.y;
            }
        }
    }
    __syncthreads();

    // ---- fused chunk stats
    if (tid < 64) {
        float P = 1.0f, L = 0.0f;
        #pragma unroll 8
        for (int t = 0; t < CHUNK; t++) {
            const float a  = a_sm [t * EPI_STR + tid];
            const float xv = xs_sm[t * EPI_STR + tid];
            L = fmaf(a, L, xv);
            P *= a;
        }
        const int b     = blockIdx.x >> 5;
        const int chunk = blockIdx.x & 31;
        const int gi    = chunk * NCH + b * Ddim + n0 + tid;
        g_P[gi] = P;
        g_L[gi] = L;
    }
}

// ---------------------------------------------------------------------------
// Kernel 3: carry combine — prefetch all P/L (independent loads), then chain
// ---------------------------------------------------------------------------
__global__ void carry_kernel()
{
    const int ch = blockIdx.x * blockDim.x + threadIdx.x;  // 0..4095
    float P[NCHUNK], L[NCHUNK];
    #pragma unroll
    for (int c = 0; c < NCHUNK; c++) {
        P[c] = g_P[c * NCH + ch];
        L[c] = g_L[c * NCH + ch];
    }
    float h = 0.0f;
    #pragma unroll
    for (int c = 0; c < NCHUNK; c++) {
        g_cin[c * NCH + ch] = h;
        h = fmaf(P[c], h, L[c]);
    }
}

// ---------------------------------------------------------------------------
// Kernel 4: final scan, 2 channels per thread (half2)
// ---------------------------------------------------------------------------
__global__ void final_scan_kernel(float* __restrict__ out)
{
    const int t = blockIdx.x * blockDim.x + threadIdx.x;   // 0..65535
    const int ch2   = t & (NCH / 2 - 1);                   // channel pair id
    const int chunk = t >> 11;
    const int b  = ch2 >> 9;
    const int d2 = ch2 & 511;                              // pair index in D
    const size_t base = ((size_t)b * Sdim + (size_t)chunk * CHUNK) * Ddim + d2 * 2;

    const int ci = chunk * NCH + b * Ddim + d2 * 2;
    float h0 = g_cin[ci], h1 = g_cin[ci + 1];

    #pragma unroll 4
    for (int i = 0; i < CHUNK; i++) {
        const size_t off = base + (size_t)i * Ddim;
        const float2 a  = __half22float2(*(const __half2*)(g_ah  + off));
        const float2 xv = __half22float2(*(const __half2*)(g_xsh + off));
        h0 = fmaf(a.x, h0, xv.x);
        h1 = fmaf(a.y, h1, xv.y);
        *(float2*)(out + off) = make_float2(h0, h1);
    }
}

// ---------------------------------------------------------------------------
// Host
// ---------------------------------------------------------------------------
extern "C" void kernel_launch(void* const* d_in, const int* in_sizes, int n_in,
                              void* d_out, int out_size)
{
    const float* x  = (const float*)d_in[0];
    const float* Wg = (const float*)d_in[1];
    const float* bg = (const float*)d_in[2];
    const float* Wv = (const float*)d_in[3];
    const float* bv = (const float*)d_in[4];
    const float* Wd = (const float*)d_in[5];
    const float* bd = (const float*)d_in[6];
    float* out = (float*)d_out;

    void *p_xh, *p_wh;
    cudaGetSymbolAddress(&p_xh, g_xh);
    cudaGetSymbolAddress(&p_wh, g_wh);
    __half* xh = (__half*)p_xh;
    __half* wh = (__half*)p_wh;

    static bool attr_set = false;
    if (!attr_set) {
        cudaFuncSetAttribute(gemm3_fp16_kernel,
                             cudaFuncAttributeMaxDynamicSharedMemorySize, GEMM_SMEM);
        attr_set = true;
    }

    const int nx4 = Mdim * Ddim / 4;     // 4,194,304
    const int nw4 = Ddim * Ddim / 4;     // 262,144
    f32_to_f16_kernel<<<(nx4 + 255) / 256, 256>>>((const float4*)x, (uint2*)xh, nx4);
    w_to_f16_kernel<<<(3 * nw4) / 256, 256>>>((const float4*)Wg, (const float4*)Wv,
                                              (const float4*)Wd, (uint2*)wh, nw4);

    dim3 g1(Mdim / 128, Ddim / 64);      // (128, 16)
    gemm3_fp16_kernel<<<g1, 256, GEMM_SMEM>>>(xh, wh, bg, bv, bd);

    carry_kernel<<<NCH / 256, 256>>>();
    final_scan_kernel<<<(NCHUNK * NCH / 2) / 256, 256>>>(out);
}